// round 8
// baseline (speedup 1.0000x reference)
#include <cuda_runtime.h>
#include <cuda_bf16.h>
#include <math.h>

// ---------------------------------------------------------------------------
// Problem constants (from reference): N=50000, E=1600000, D=64, R=4, L=4, B=256
// ---------------------------------------------------------------------------
#define DD 64
#define RR 4
#define NCOLS 320          // R*D (relation-transformed) + D (self-loop)
#define NMAX 50048
#define EMAX 1600512

// Scratch (static __device__ allocation is the sanctioned workaround)
__device__ float g_X[(size_t)NMAX * NCOLS];   // per-layer transformed features [N,320]
__device__ float g_h0[(size_t)NMAX * DD];
__device__ float g_h1[(size_t)NMAX * DD];
__device__ int   g_rowptr[NMAX + 1];
__device__ int   g_cnt[NMAX];
__device__ int   g_fill[NMAX];
__device__ int   g_off2[EMAX];                // src*320 + etype*64, CSR-ordered by dst
__device__ int   g_src2[EMAX];                // src, CSR-ordered by dst
__device__ float g_el[NMAX];
__device__ float g_er[NMAX];
__device__ float g_zd[NMAX];
__device__ float g_vl[DD];
__device__ float g_vr[DD];
__device__ float g_vd[DD];

// ---------------------------------------------------------------------------
// Preprocessing: CSR by destination
// ---------------------------------------------------------------------------
__global__ void k_zero_int(int* p, int n) {
    int i = blockIdx.x * blockDim.x + threadIdx.x;
    if (i < n) p[i] = 0;
}

__global__ void k_hist(const int* __restrict__ dst, int* __restrict__ cnt, int E) {
    int e = blockIdx.x * blockDim.x + threadIdx.x;
    if (e < E) atomicAdd(&cnt[dst[e]], 1);
}

__global__ void __launch_bounds__(1024) k_scan(const int* __restrict__ cnt,
                                               int* __restrict__ rowptr, int n) {
    __shared__ int sdata[1024];
    __shared__ int carry;
    int t = threadIdx.x;
    if (t == 0) { carry = 0; rowptr[0] = 0; }
    __syncthreads();
    for (int base = 0; base < n; base += 1024) {
        int i = base + t;
        int val = (i < n) ? cnt[i] : 0;
        sdata[t] = val;
        __syncthreads();
        #pragma unroll
        for (int off = 1; off < 1024; off <<= 1) {
            int y = (t >= off) ? sdata[t - off] : 0;
            __syncthreads();
            sdata[t] += y;
            __syncthreads();
        }
        int inc = sdata[t];
        int c = carry;
        if (i < n) rowptr[i + 1] = c + inc;
        __syncthreads();
        if (t == 1023) carry = c + sdata[1023];
        __syncthreads();
    }
}

__global__ void k_scatter(const int* __restrict__ src, const int* __restrict__ dst,
                          const int* __restrict__ et, const int* __restrict__ rowptr,
                          int* __restrict__ fill, int* __restrict__ off2,
                          int* __restrict__ src2, int E) {
    int e = blockIdx.x * blockDim.x + threadIdx.x;
    if (e >= E) return;
    int d = dst[e];
    int p = rowptr[d] + atomicAdd(&fill[d], 1);
    int s = src[e];
    off2[p] = s * NCOLS + et[e] * DD;
    src2[p] = s;
}

// ---------------------------------------------------------------------------
// Fused per-layer GEMM: X[n, 0:256] = h[n] @ Wrel[l] (4 relation blocks),
//                       X[n, 256:320] = h[n] @ Wloop[l]
// Thread-per-node, h row in registers, W tile broadcast from shared,
// packed fma.rn.f32x2 (2 fp32 MACs / FMA-pipe op).
// ---------------------------------------------------------------------------
__global__ void __launch_bounds__(128) k_gemm(const float* __restrict__ h,
                                              const float* __restrict__ Wrel_l,
                                              const float* __restrict__ Wloop_l,
                                              float* __restrict__ X, int N) {
    __shared__ float Ws[DD * DD];          // one [64,64] weight block (16 KB)
    int t = threadIdx.x;
    int node = blockIdx.x * 128 + t;
    bool valid = node < N;

    float hreg[DD];
    if (valid) {
        const float4* hp = reinterpret_cast<const float4*>(h + (size_t)node * DD);
        #pragma unroll
        for (int i = 0; i < 16; i++) {
            float4 v = hp[i];
            hreg[4 * i + 0] = v.x; hreg[4 * i + 1] = v.y;
            hreg[4 * i + 2] = v.z; hreg[4 * i + 3] = v.w;
        }
    } else {
        #pragma unroll
        for (int i = 0; i < DD; i++) hreg[i] = 0.f;
    }

    for (int chunk = 0; chunk < 5; chunk++) {
        const float* Wsrc = (chunk < 4) ? (Wrel_l + chunk * (DD * DD)) : Wloop_l;
        __syncthreads();
        #pragma unroll
        for (int i = 0; i < 8; i++) {     // 4096 floats = 1024 float4 / 128 threads
            reinterpret_cast<float4*>(Ws)[t + i * 128] =
                reinterpret_cast<const float4*>(Wsrc)[t + i * 128];
        }
        __syncthreads();

        #pragma unroll 1
        for (int cg = 0; cg < 8; cg++) {  // 8 output columns per group
            unsigned long long a0 = 0, a1 = 0, a2 = 0, a3 = 0;
            const float* wbase = Ws + cg * 8;
            #pragma unroll
            for (int k = 0; k < DD; k++) {
                unsigned long long h2;
                asm("mov.b64 %0, {%1, %1};" : "=l"(h2) : "f"(hreg[k]));
                ulonglong2 w01 = *reinterpret_cast<const ulonglong2*>(wbase + k * DD);
                ulonglong2 w23 = *reinterpret_cast<const ulonglong2*>(wbase + k * DD + 4);
                asm("fma.rn.f32x2 %0, %1, %2, %0;" : "+l"(a0) : "l"(h2), "l"(w01.x));
                asm("fma.rn.f32x2 %0, %1, %2, %0;" : "+l"(a1) : "l"(h2), "l"(w01.y));
                asm("fma.rn.f32x2 %0, %1, %2, %0;" : "+l"(a2) : "l"(h2), "l"(w23.x));
                asm("fma.rn.f32x2 %0, %1, %2, %0;" : "+l"(a3) : "l"(h2), "l"(w23.y));
            }
            if (valid) {
                ulonglong2* op = reinterpret_cast<ulonglong2*>(
                    X + (size_t)node * NCOLS + chunk * DD + cg * 8);
                op[0] = make_ulonglong2(a0, a1);
                op[1] = make_ulonglong2(a2, a3);
            }
        }
    }
}

// ---------------------------------------------------------------------------
// RGCN aggregation: one block (64 threads = feature dims) per node.
// acc = selfloop + bias + sum over CSR in-edges of X[src*320 + et*64 + dim]; ReLU.
// 4-way unroll with independent accumulators to expose memory-level parallelism.
// ---------------------------------------------------------------------------
__global__ void __launch_bounds__(64) k_agg(const float* __restrict__ X,
                                            const float* __restrict__ brel_l,
                                            const int* __restrict__ rowptr,
                                            const int* __restrict__ off2,
                                            float* __restrict__ hout, int N) {
    int v = blockIdx.x;
    if (v >= N) return;
    int dim = threadIdx.x;
    float acc0 = X[(size_t)v * NCOLS + RR * DD + dim] + brel_l[dim];
    float acc1 = 0.f, acc2 = 0.f, acc3 = 0.f;
    int e = rowptr[v], end = rowptr[v + 1];
    for (; e + 4 <= end; e += 4) {
        int o0 = off2[e], o1 = off2[e + 1], o2 = off2[e + 2], o3 = off2[e + 3];
        acc0 += X[o0 + dim];
        acc1 += X[o1 + dim];
        acc2 += X[o2 + dim];
        acc3 += X[o3 + dim];
    }
    for (; e < end; e++) acc0 += X[off2[e] + dim];
    float r = (acc0 + acc1) + (acc2 + acc3);
    hout[(size_t)v * DD + dim] = r > 0.f ? r : 0.f;
}

// ---------------------------------------------------------------------------
// GAT head, algebraically collapsed:
//   vl = Wg@al, vr = Wg@ar, vd = Wg@Wd   (tiny)
//   el/er/zd = h @ {vl, vr, vd}          (per node)
//   per node: softmax over in-edges of leaky(el[src]+er[v]); s_v = sum a_e*zd[src]
//   out[gid[v]] += s_v  (pool + dense head fused)
// ---------------------------------------------------------------------------
__global__ void __launch_bounds__(64) k_vecs(const float* __restrict__ Wg,
                                             const float* __restrict__ al,
                                             const float* __restrict__ ar,
                                             const float* __restrict__ Wd,
                                             float* __restrict__ vl,
                                             float* __restrict__ vr,
                                             float* __restrict__ vd) {
    int k = threadIdx.x;
    float sl = 0.f, sr = 0.f, sd = 0.f;
    #pragma unroll
    for (int o = 0; o < DD; o++) {
        float w = Wg[k * DD + o];
        sl += w * al[o];
        sr += w * ar[o];
        sd += w * Wd[o];
    }
    vl[k] = sl; vr[k] = sr; vd[k] = sd;
}

__global__ void __launch_bounds__(256) k_elerzd(const float* __restrict__ h,
                                                const float* __restrict__ vl,
                                                const float* __restrict__ vr,
                                                const float* __restrict__ vd,
                                                float* __restrict__ el,
                                                float* __restrict__ er,
                                                float* __restrict__ zd, int N) {
    int n = blockIdx.x * 256 + threadIdx.x;
    if (n >= N) return;
    const float* hp = h + (size_t)n * DD;
    float sl = 0.f, sr = 0.f, sd = 0.f;
    #pragma unroll
    for (int k = 0; k < DD; k++) {
        float hk = hp[k];
        sl += hk * vl[k];
        sr += hk * vr[k];
        sd += hk * vd[k];
    }
    el[n] = sl; er[n] = sr; zd[n] = sd;
}

__global__ void k_outinit(const float* __restrict__ bd, float* __restrict__ out, int B) {
    int b = blockIdx.x * blockDim.x + threadIdx.x;
    if (b < B) out[b] = bd[0];
}

__global__ void __launch_bounds__(64) k_gat(const float* __restrict__ el,
                                            const float* __restrict__ er,
                                            const float* __restrict__ zd,
                                            const int* __restrict__ rowptr,
                                            const int* __restrict__ src2,
                                            const int* __restrict__ gids,
                                            float* __restrict__ out, int N) {
    __shared__ float red[64];
    __shared__ float red2[64];
    int v = blockIdx.x;
    if (v >= N) return;
    int t = threadIdx.x;
    float erv = er[v];
    int beg = rowptr[v], end = rowptr[v + 1];

    // pass 1: segment max of leaky(el[src]+er[v])
    float m = -3.0e38f;
    for (int e = beg + t; e < end; e += 64) {
        float x = el[src2[e]] + erv;
        x = x > 0.f ? x : 0.2f * x;
        m = fmaxf(m, x);
    }
    red[t] = m;
    __syncthreads();
    #pragma unroll
    for (int off = 32; off > 0; off >>= 1) {
        if (t < off) red[t] = fmaxf(red[t], red[t + off]);
        __syncthreads();
    }
    m = red[0];
    __syncthreads();

    // pass 2: denominator + weighted sum of zd[src]
    float den = 0.f, num = 0.f;
    for (int e = beg + t; e < end; e += 64) {
        int s = src2[e];
        float x = el[s] + erv;
        x = x > 0.f ? x : 0.2f * x;
        float w = expf(x - m);
        den += w;
        num += w * zd[s];
    }
    red[t] = den; red2[t] = num;
    __syncthreads();
    #pragma unroll
    for (int off = 32; off > 0; off >>= 1) {
        if (t < off) { red[t] += red[t + off]; red2[t] += red2[t + off]; }
        __syncthreads();
    }
    if (t == 0) {
        float s = red2[0] / fmaxf(red[0], 1e-9f);
        atomicAdd(&out[gids[v]], s);
    }
}

// ---------------------------------------------------------------------------
// Launch: build CSR once, run 4 fused layers, GAT+pool+dense, all in-stream.
// ---------------------------------------------------------------------------
extern "C" void kernel_launch(void* const* d_in, const int* in_sizes, int n_in,
                              void* d_out, int out_size) {
    const float* h_in   = (const float*)d_in[0];
    const float* Wrel   = (const float*)d_in[1];
    const float* Wloop  = (const float*)d_in[2];
    const float* brel   = (const float*)d_in[3];
    const float* Wg     = (const float*)d_in[4];
    const float* al     = (const float*)d_in[5];
    const float* ar     = (const float*)d_in[6];
    const float* Wd     = (const float*)d_in[7];
    const float* bd     = (const float*)d_in[8];
    const int*   src    = (const int*)d_in[9];
    const int*   dst    = (const int*)d_in[10];
    const int*   etypes = (const int*)d_in[11];
    const int*   gids   = (const int*)d_in[12];
    float*       out    = (float*)d_out;

    const int N = in_sizes[0] / DD;
    const int E = in_sizes[9];
    const int L = in_sizes[2] / (DD * DD);
    const int B = out_size;

    // Resolve scratch symbol addresses (not a stream op; capture-safe).
    float *X, *h0, *h1, *elp, *erp, *zdp, *vl, *vr, *vd;
    int *rowptr, *cnt, *fill, *off2, *src2;
    cudaGetSymbolAddress((void**)&X,      g_X);
    cudaGetSymbolAddress((void**)&h0,     g_h0);
    cudaGetSymbolAddress((void**)&h1,     g_h1);
    cudaGetSymbolAddress((void**)&rowptr, g_rowptr);
    cudaGetSymbolAddress((void**)&cnt,    g_cnt);
    cudaGetSymbolAddress((void**)&fill,   g_fill);
    cudaGetSymbolAddress((void**)&off2,   g_off2);
    cudaGetSymbolAddress((void**)&src2,   g_src2);
    cudaGetSymbolAddress((void**)&elp,    g_el);
    cudaGetSymbolAddress((void**)&erp,    g_er);
    cudaGetSymbolAddress((void**)&zdp,    g_zd);
    cudaGetSymbolAddress((void**)&vl,     g_vl);
    cudaGetSymbolAddress((void**)&vr,     g_vr);
    cudaGetSymbolAddress((void**)&vd,     g_vd);

    const int EB = (E + 255) / 256;
    const int NB = (N + 255) / 256;

    // --- CSR by dst ---
    k_zero_int<<<NB, 256>>>(cnt, N);
    k_zero_int<<<NB, 256>>>(fill, N);
    k_hist<<<EB, 256>>>(dst, cnt, E);
    k_scan<<<1, 1024>>>(cnt, rowptr, N);
    k_scatter<<<EB, 256>>>(src, dst, etypes, rowptr, fill, off2, src2, E);

    // --- stacked RGCN layers ---
    const float* hcur = h_in;
    float* hnext = h0;
    const int GB = (N + 127) / 128;
    for (int l = 0; l < L; l++) {
        k_gemm<<<GB, 128>>>(hcur, Wrel + (size_t)l * RR * DD * DD,
                            Wloop + (size_t)l * DD * DD, X, N);
        k_agg<<<N, 64>>>(X, brel + (size_t)l * DD, rowptr, off2, hnext, N);
        hcur = hnext;
        hnext = (hnext == h0) ? h1 : h0;
    }

    // --- GAT head + SumPooling + dense, collapsed to scalars per node ---
    k_vecs<<<1, 64>>>(Wg, al, ar, Wd, vl, vr, vd);
    k_elerzd<<<NB, 256>>>(hcur, vl, vr, vd, elp, erp, zdp, N);
    k_outinit<<<1, 256>>>(bd, out, B);
    k_gat<<<N, 64>>>(elp, erp, zdp, rowptr, src2, gids, out, N);
}

// round 9
// speedup vs baseline: 1.0006x; 1.0006x over previous
#include <cuda_runtime.h>
#include <cuda_bf16.h>
#include <math.h>

// ---------------------------------------------------------------------------
// Problem constants (from reference): N=50000, E=1600000, D=64, R=4, L=4, B=256
// ---------------------------------------------------------------------------
#define DD 64
#define RR 4
#define NCOLS 320          // R*D (relation-transformed) + D (self-loop)
#define NMAX 50048
#define EMAX 1600512

// Scratch (static __device__ allocation is the sanctioned workaround)
__device__ float g_X[(size_t)NMAX * NCOLS];   // per-layer transformed features [N,320]
__device__ float g_h0[(size_t)NMAX * DD];
__device__ float g_h1[(size_t)NMAX * DD];
__device__ int   g_rowptr[NMAX + 1];
__device__ int   g_cnt[NMAX];
__device__ int   g_fill[NMAX];
__device__ int   g_off2[EMAX];                // src*320 + etype*64, CSR-ordered by dst
__device__ int   g_src2[EMAX];                // src, CSR-ordered by dst
__device__ float g_el[NMAX];
__device__ float g_er[NMAX];
__device__ float g_zd[NMAX];
__device__ float g_vl[DD];
__device__ float g_vr[DD];
__device__ float g_vd[DD];

// ---------------------------------------------------------------------------
// Preprocessing: CSR by destination
// ---------------------------------------------------------------------------
__global__ void k_zero_int(int* p, int n) {
    int i = blockIdx.x * blockDim.x + threadIdx.x;
    if (i < n) p[i] = 0;
}

__global__ void k_hist(const int* __restrict__ dst, int* __restrict__ cnt, int E) {
    int e = blockIdx.x * blockDim.x + threadIdx.x;
    if (e < E) atomicAdd(&cnt[dst[e]], 1);
}

__global__ void __launch_bounds__(1024) k_scan(const int* __restrict__ cnt,
                                               int* __restrict__ rowptr, int n) {
    __shared__ int sdata[1024];
    __shared__ int carry;
    int t = threadIdx.x;
    if (t == 0) { carry = 0; rowptr[0] = 0; }
    __syncthreads();
    for (int base = 0; base < n; base += 1024) {
        int i = base + t;
        int val = (i < n) ? cnt[i] : 0;
        sdata[t] = val;
        __syncthreads();
        #pragma unroll
        for (int off = 1; off < 1024; off <<= 1) {
            int y = (t >= off) ? sdata[t - off] : 0;
            __syncthreads();
            sdata[t] += y;
            __syncthreads();
        }
        int inc = sdata[t];
        int c = carry;
        if (i < n) rowptr[i + 1] = c + inc;
        __syncthreads();
        if (t == 1023) carry = c + sdata[1023];
        __syncthreads();
    }
}

__global__ void k_scatter(const int* __restrict__ src, const int* __restrict__ dst,
                          const int* __restrict__ et, const int* __restrict__ rowptr,
                          int* __restrict__ fill, int* __restrict__ off2,
                          int* __restrict__ src2, int E) {
    int e = blockIdx.x * blockDim.x + threadIdx.x;
    if (e >= E) return;
    int d = dst[e];
    int p = rowptr[d] + atomicAdd(&fill[d], 1);
    int s = src[e];
    off2[p] = s * NCOLS + et[e] * DD;
    src2[p] = s;
}

// ---------------------------------------------------------------------------
// Fused per-layer GEMM: X[n, 0:256] = h[n] @ Wrel[l] (4 relation blocks),
//                       X[n, 256:320] = h[n] @ Wloop[l]
// Thread-per-node, h row in registers, W tile broadcast from shared,
// packed fma.rn.f32x2 (2 fp32 MACs / FMA-pipe op).
// ---------------------------------------------------------------------------
__global__ void __launch_bounds__(128) k_gemm(const float* __restrict__ h,
                                              const float* __restrict__ Wrel_l,
                                              const float* __restrict__ Wloop_l,
                                              float* __restrict__ X, int N) {
    __shared__ float Ws[DD * DD];          // one [64,64] weight block (16 KB)
    int t = threadIdx.x;
    int node = blockIdx.x * 128 + t;
    bool valid = node < N;

    float hreg[DD];
    if (valid) {
        const float4* hp = reinterpret_cast<const float4*>(h + (size_t)node * DD);
        #pragma unroll
        for (int i = 0; i < 16; i++) {
            float4 v = hp[i];
            hreg[4 * i + 0] = v.x; hreg[4 * i + 1] = v.y;
            hreg[4 * i + 2] = v.z; hreg[4 * i + 3] = v.w;
        }
    } else {
        #pragma unroll
        for (int i = 0; i < DD; i++) hreg[i] = 0.f;
    }

    for (int chunk = 0; chunk < 5; chunk++) {
        const float* Wsrc = (chunk < 4) ? (Wrel_l + chunk * (DD * DD)) : Wloop_l;
        __syncthreads();
        #pragma unroll
        for (int i = 0; i < 8; i++) {     // 4096 floats = 1024 float4 / 128 threads
            reinterpret_cast<float4*>(Ws)[t + i * 128] =
                reinterpret_cast<const float4*>(Wsrc)[t + i * 128];
        }
        __syncthreads();

        #pragma unroll 1
        for (int cg = 0; cg < 8; cg++) {  // 8 output columns per group
            unsigned long long a0 = 0, a1 = 0, a2 = 0, a3 = 0;
            const float* wbase = Ws + cg * 8;
            #pragma unroll
            for (int k = 0; k < DD; k++) {
                unsigned long long h2;
                asm("mov.b64 %0, {%1, %1};" : "=l"(h2) : "f"(hreg[k]));
                ulonglong2 w01 = *reinterpret_cast<const ulonglong2*>(wbase + k * DD);
                ulonglong2 w23 = *reinterpret_cast<const ulonglong2*>(wbase + k * DD + 4);
                asm("fma.rn.f32x2 %0, %1, %2, %0;" : "+l"(a0) : "l"(h2), "l"(w01.x));
                asm("fma.rn.f32x2 %0, %1, %2, %0;" : "+l"(a1) : "l"(h2), "l"(w01.y));
                asm("fma.rn.f32x2 %0, %1, %2, %0;" : "+l"(a2) : "l"(h2), "l"(w23.x));
                asm("fma.rn.f32x2 %0, %1, %2, %0;" : "+l"(a3) : "l"(h2), "l"(w23.y));
            }
            if (valid) {
                ulonglong2* op = reinterpret_cast<ulonglong2*>(
                    X + (size_t)node * NCOLS + chunk * DD + cg * 8);
                op[0] = make_ulonglong2(a0, a1);
                op[1] = make_ulonglong2(a2, a3);
            }
        }
    }
}

// ---------------------------------------------------------------------------
// RGCN aggregation: one block (64 threads = feature dims) per node.
// acc = selfloop + bias + sum over CSR in-edges of X[src*320 + et*64 + dim]; ReLU.
// 4-way unroll with independent accumulators to expose memory-level parallelism.
// ---------------------------------------------------------------------------
__global__ void __launch_bounds__(64) k_agg(const float* __restrict__ X,
                                            const float* __restrict__ brel_l,
                                            const int* __restrict__ rowptr,
                                            const int* __restrict__ off2,
                                            float* __restrict__ hout, int N) {
    int v = blockIdx.x;
    if (v >= N) return;
    int dim = threadIdx.x;
    float acc0 = X[(size_t)v * NCOLS + RR * DD + dim] + brel_l[dim];
    float acc1 = 0.f, acc2 = 0.f, acc3 = 0.f;
    int e = rowptr[v], end = rowptr[v + 1];
    for (; e + 4 <= end; e += 4) {
        int o0 = off2[e], o1 = off2[e + 1], o2 = off2[e + 2], o3 = off2[e + 3];
        acc0 += X[o0 + dim];
        acc1 += X[o1 + dim];
        acc2 += X[o2 + dim];
        acc3 += X[o3 + dim];
    }
    for (; e < end; e++) acc0 += X[off2[e] + dim];
    float r = (acc0 + acc1) + (acc2 + acc3);
    hout[(size_t)v * DD + dim] = r > 0.f ? r : 0.f;
}

// ---------------------------------------------------------------------------
// GAT head, algebraically collapsed:
//   vl = Wg@al, vr = Wg@ar, vd = Wg@Wd   (tiny)
//   el/er/zd = h @ {vl, vr, vd}          (per node)
//   per node: softmax over in-edges of leaky(el[src]+er[v]); s_v = sum a_e*zd[src]
//   out[gid[v]] += s_v  (pool + dense head fused)
// ---------------------------------------------------------------------------
__global__ void __launch_bounds__(64) k_vecs(const float* __restrict__ Wg,
                                             const float* __restrict__ al,
                                             const float* __restrict__ ar,
                                             const float* __restrict__ Wd,
                                             float* __restrict__ vl,
                                             float* __restrict__ vr,
                                             float* __restrict__ vd) {
    int k = threadIdx.x;
    float sl = 0.f, sr = 0.f, sd = 0.f;
    #pragma unroll
    for (int o = 0; o < DD; o++) {
        float w = Wg[k * DD + o];
        sl += w * al[o];
        sr += w * ar[o];
        sd += w * Wd[o];
    }
    vl[k] = sl; vr[k] = sr; vd[k] = sd;
}

__global__ void __launch_bounds__(256) k_elerzd(const float* __restrict__ h,
                                                const float* __restrict__ vl,
                                                const float* __restrict__ vr,
                                                const float* __restrict__ vd,
                                                float* __restrict__ el,
                                                float* __restrict__ er,
                                                float* __restrict__ zd, int N) {
    int n = blockIdx.x * 256 + threadIdx.x;
    if (n >= N) return;
    const float* hp = h + (size_t)n * DD;
    float sl = 0.f, sr = 0.f, sd = 0.f;
    #pragma unroll
    for (int k = 0; k < DD; k++) {
        float hk = hp[k];
        sl += hk * vl[k];
        sr += hk * vr[k];
        sd += hk * vd[k];
    }
    el[n] = sl; er[n] = sr; zd[n] = sd;
}

__global__ void k_outinit(const float* __restrict__ bd, float* __restrict__ out, int B) {
    int b = blockIdx.x * blockDim.x + threadIdx.x;
    if (b < B) out[b] = bd[0];
}

__global__ void __launch_bounds__(64) k_gat(const float* __restrict__ el,
                                            const float* __restrict__ er,
                                            const float* __restrict__ zd,
                                            const int* __restrict__ rowptr,
                                            const int* __restrict__ src2,
                                            const int* __restrict__ gids,
                                            float* __restrict__ out, int N) {
    __shared__ float red[64];
    __shared__ float red2[64];
    int v = blockIdx.x;
    if (v >= N) return;
    int t = threadIdx.x;
    float erv = er[v];
    int beg = rowptr[v], end = rowptr[v + 1];

    // pass 1: segment max of leaky(el[src]+er[v])
    float m = -3.0e38f;
    for (int e = beg + t; e < end; e += 64) {
        float x = el[src2[e]] + erv;
        x = x > 0.f ? x : 0.2f * x;
        m = fmaxf(m, x);
    }
    red[t] = m;
    __syncthreads();
    #pragma unroll
    for (int off = 32; off > 0; off >>= 1) {
        if (t < off) red[t] = fmaxf(red[t], red[t + off]);
        __syncthreads();
    }
    m = red[0];
    __syncthreads();

    // pass 2: denominator + weighted sum of zd[src]
    float den = 0.f, num = 0.f;
    for (int e = beg + t; e < end; e += 64) {
        int s = src2[e];
        float x = el[s] + erv;
        x = x > 0.f ? x : 0.2f * x;
        float w = expf(x - m);
        den += w;
        num += w * zd[s];
    }
    red[t] = den; red2[t] = num;
    __syncthreads();
    #pragma unroll
    for (int off = 32; off > 0; off >>= 1) {
        if (t < off) { red[t] += red[t + off]; red2[t] += red2[t + off]; }
        __syncthreads();
    }
    if (t == 0) {
        float s = red2[0] / fmaxf(red[0], 1e-9f);
        atomicAdd(&out[gids[v]], s);
    }
}

// ---------------------------------------------------------------------------
// Launch: build CSR once, run 4 fused layers, GAT+pool+dense, all in-stream.
// ---------------------------------------------------------------------------
extern "C" void kernel_launch(void* const* d_in, const int* in_sizes, int n_in,
                              void* d_out, int out_size) {
    const float* h_in   = (const float*)d_in[0];
    const float* Wrel   = (const float*)d_in[1];
    const float* Wloop  = (const float*)d_in[2];
    const float* brel   = (const float*)d_in[3];
    const float* Wg     = (const float*)d_in[4];
    const float* al     = (const float*)d_in[5];
    const float* ar     = (const float*)d_in[6];
    const float* Wd     = (const float*)d_in[7];
    const float* bd     = (const float*)d_in[8];
    const int*   src    = (const int*)d_in[9];
    const int*   dst    = (const int*)d_in[10];
    const int*   etypes = (const int*)d_in[11];
    const int*   gids   = (const int*)d_in[12];
    float*       out    = (float*)d_out;

    const int N = in_sizes[0] / DD;
    const int E = in_sizes[9];
    const int L = in_sizes[2] / (DD * DD);
    const int B = out_size;

    // Resolve scratch symbol addresses (not a stream op; capture-safe).
    float *X, *h0, *h1, *elp, *erp, *zdp, *vl, *vr, *vd;
    int *rowptr, *cnt, *fill, *off2, *src2;
    cudaGetSymbolAddress((void**)&X,      g_X);
    cudaGetSymbolAddress((void**)&h0,     g_h0);
    cudaGetSymbolAddress((void**)&h1,     g_h1);
    cudaGetSymbolAddress((void**)&rowptr, g_rowptr);
    cudaGetSymbolAddress((void**)&cnt,    g_cnt);
    cudaGetSymbolAddress((void**)&fill,   g_fill);
    cudaGetSymbolAddress((void**)&off2,   g_off2);
    cudaGetSymbolAddress((void**)&src2,   g_src2);
    cudaGetSymbolAddress((void**)&elp,    g_el);
    cudaGetSymbolAddress((void**)&erp,    g_er);
    cudaGetSymbolAddress((void**)&zdp,    g_zd);
    cudaGetSymbolAddress((void**)&vl,     g_vl);
    cudaGetSymbolAddress((void**)&vr,     g_vr);
    cudaGetSymbolAddress((void**)&vd,     g_vd);

    const int EB = (E + 255) / 256;
    const int NB = (N + 255) / 256;

    // --- CSR by dst ---
    k_zero_int<<<NB, 256>>>(cnt, N);
    k_zero_int<<<NB, 256>>>(fill, N);
    k_hist<<<EB, 256>>>(dst, cnt, E);
    k_scan<<<1, 1024>>>(cnt, rowptr, N);
    k_scatter<<<EB, 256>>>(src, dst, etypes, rowptr, fill, off2, src2, E);

    // --- stacked RGCN layers ---
    const float* hcur = h_in;
    float* hnext = h0;
    const int GB = (N + 127) / 128;
    for (int l = 0; l < L; l++) {
        k_gemm<<<GB, 128>>>(hcur, Wrel + (size_t)l * RR * DD * DD,
                            Wloop + (size_t)l * DD * DD, X, N);
        k_agg<<<N, 64>>>(X, brel + (size_t)l * DD, rowptr, off2, hnext, N);
        hcur = hnext;
        hnext = (hnext == h0) ? h1 : h0;
    }

    // --- GAT head + SumPooling + dense, collapsed to scalars per node ---
    k_vecs<<<1, 64>>>(Wg, al, ar, Wd, vl, vr, vd);
    k_elerzd<<<NB, 256>>>(hcur, vl, vr, vd, elp, erp, zdp, N);
    k_outinit<<<1, 256>>>(bd, out, B);
    k_gat<<<N, 64>>>(elp, erp, zdp, rowptr, src2, gids, out, N);
}

// round 10
// speedup vs baseline: 1.0047x; 1.0041x over previous
#include <cuda_runtime.h>
#include <cuda_bf16.h>
#include <math.h>

// ---------------------------------------------------------------------------
// Problem constants (from reference): N=50000, E=1600000, D=64, R=4, L=4, B=256
// ---------------------------------------------------------------------------
#define DD 64
#define RR 4
#define NCOLS 320          // R*D (relation-transformed) + D (self-loop)
#define NMAX 50048
#define EMAX 1600512

// Scratch (static __device__ allocation is the sanctioned workaround)
__device__ float g_X[(size_t)NMAX * NCOLS];   // per-layer transformed features [N,320]
__device__ float g_h0[(size_t)NMAX * DD];
__device__ float g_h1[(size_t)NMAX * DD];
__device__ int   g_rowptr[NMAX + 1];
__device__ int   g_cnt[NMAX];
__device__ int   g_fill[NMAX];
__device__ int   g_off2[EMAX];                // src*320 + etype*64, CSR-ordered by dst
__device__ int   g_src2[EMAX];                // src, CSR-ordered by dst
__device__ float g_el[NMAX];
__device__ float g_er[NMAX];
__device__ float g_zd[NMAX];
__device__ float g_vl[DD];
__device__ float g_vr[DD];
__device__ float g_vd[DD];

// ---------------------------------------------------------------------------
// Preprocessing: CSR by destination
// ---------------------------------------------------------------------------
__global__ void k_zero_int(int* p, int n) {
    int i = blockIdx.x * blockDim.x + threadIdx.x;
    if (i < n) p[i] = 0;
}

__global__ void k_hist(const int* __restrict__ dst, int* __restrict__ cnt, int E) {
    int e = blockIdx.x * blockDim.x + threadIdx.x;
    if (e < E) atomicAdd(&cnt[dst[e]], 1);
}

__global__ void __launch_bounds__(1024) k_scan(const int* __restrict__ cnt,
                                               int* __restrict__ rowptr, int n) {
    __shared__ int sdata[1024];
    __shared__ int carry;
    int t = threadIdx.x;
    if (t == 0) { carry = 0; rowptr[0] = 0; }
    __syncthreads();
    for (int base = 0; base < n; base += 1024) {
        int i = base + t;
        int val = (i < n) ? cnt[i] : 0;
        sdata[t] = val;
        __syncthreads();
        #pragma unroll
        for (int off = 1; off < 1024; off <<= 1) {
            int y = (t >= off) ? sdata[t - off] : 0;
            __syncthreads();
            sdata[t] += y;
            __syncthreads();
        }
        int inc = sdata[t];
        int c = carry;
        if (i < n) rowptr[i + 1] = c + inc;
        __syncthreads();
        if (t == 1023) carry = c + sdata[1023];
        __syncthreads();
    }
}

__global__ void k_scatter(const int* __restrict__ src, const int* __restrict__ dst,
                          const int* __restrict__ et, const int* __restrict__ rowptr,
                          int* __restrict__ fill, int* __restrict__ off2,
                          int* __restrict__ src2, int E) {
    int e = blockIdx.x * blockDim.x + threadIdx.x;
    if (e >= E) return;
    int d = dst[e];
    int p = rowptr[d] + atomicAdd(&fill[d], 1);
    int s = src[e];
    off2[p] = s * NCOLS + et[e] * DD;
    src2[p] = s;
}

// ---------------------------------------------------------------------------
// Fused per-layer GEMM: X[n, 0:256] = h[n] @ Wrel[l] (4 relation blocks),
//                       X[n, 256:320] = h[n] @ Wloop[l]
// Thread-per-node, h row in registers, W tile broadcast from shared,
// packed fma.rn.f32x2 (2 fp32 MACs / FMA-pipe op).
// ---------------------------------------------------------------------------
__global__ void __launch_bounds__(128) k_gemm(const float* __restrict__ h,
                                              const float* __restrict__ Wrel_l,
                                              const float* __restrict__ Wloop_l,
                                              float* __restrict__ X, int N) {
    __shared__ float Ws[DD * DD];          // one [64,64] weight block (16 KB)
    int t = threadIdx.x;
    int node = blockIdx.x * 128 + t;
    bool valid = node < N;

    float hreg[DD];
    if (valid) {
        const float4* hp = reinterpret_cast<const float4*>(h + (size_t)node * DD);
        #pragma unroll
        for (int i = 0; i < 16; i++) {
            float4 v = hp[i];
            hreg[4 * i + 0] = v.x; hreg[4 * i + 1] = v.y;
            hreg[4 * i + 2] = v.z; hreg[4 * i + 3] = v.w;
        }
    } else {
        #pragma unroll
        for (int i = 0; i < DD; i++) hreg[i] = 0.f;
    }

    for (int chunk = 0; chunk < 5; chunk++) {
        const float* Wsrc = (chunk < 4) ? (Wrel_l + chunk * (DD * DD)) : Wloop_l;
        __syncthreads();
        #pragma unroll
        for (int i = 0; i < 8; i++) {     // 4096 floats = 1024 float4 / 128 threads
            reinterpret_cast<float4*>(Ws)[t + i * 128] =
                reinterpret_cast<const float4*>(Wsrc)[t + i * 128];
        }
        __syncthreads();

        #pragma unroll 1
        for (int cg = 0; cg < 8; cg++) {  // 8 output columns per group
            unsigned long long a0 = 0, a1 = 0, a2 = 0, a3 = 0;
            const float* wbase = Ws + cg * 8;
            #pragma unroll
            for (int k = 0; k < DD; k++) {
                unsigned long long h2;
                asm("mov.b64 %0, {%1, %1};" : "=l"(h2) : "f"(hreg[k]));
                ulonglong2 w01 = *reinterpret_cast<const ulonglong2*>(wbase + k * DD);
                ulonglong2 w23 = *reinterpret_cast<const ulonglong2*>(wbase + k * DD + 4);
                asm("fma.rn.f32x2 %0, %1, %2, %0;" : "+l"(a0) : "l"(h2), "l"(w01.x));
                asm("fma.rn.f32x2 %0, %1, %2, %0;" : "+l"(a1) : "l"(h2), "l"(w01.y));
                asm("fma.rn.f32x2 %0, %1, %2, %0;" : "+l"(a2) : "l"(h2), "l"(w23.x));
                asm("fma.rn.f32x2 %0, %1, %2, %0;" : "+l"(a3) : "l"(h2), "l"(w23.y));
            }
            if (valid) {
                ulonglong2* op = reinterpret_cast<ulonglong2*>(
                    X + (size_t)node * NCOLS + chunk * DD + cg * 8);
                op[0] = make_ulonglong2(a0, a1);
                op[1] = make_ulonglong2(a2, a3);
            }
        }
    }
}

// ---------------------------------------------------------------------------
// RGCN aggregation: one block (64 threads = feature dims) per node.
// acc = selfloop + bias + sum over CSR in-edges of X[src*320 + et*64 + dim]; ReLU.
// 4-way unroll with independent accumulators to expose memory-level parallelism.
// ---------------------------------------------------------------------------
__global__ void __launch_bounds__(64) k_agg(const float* __restrict__ X,
                                            const float* __restrict__ brel_l,
                                            const int* __restrict__ rowptr,
                                            const int* __restrict__ off2,
                                            float* __restrict__ hout, int N) {
    int v = blockIdx.x;
    if (v >= N) return;
    int dim = threadIdx.x;
    float acc0 = X[(size_t)v * NCOLS + RR * DD + dim] + brel_l[dim];
    float acc1 = 0.f, acc2 = 0.f, acc3 = 0.f;
    int e = rowptr[v], end = rowptr[v + 1];
    for (; e + 4 <= end; e += 4) {
        int o0 = off2[e], o1 = off2[e + 1], o2 = off2[e + 2], o3 = off2[e + 3];
        acc0 += X[o0 + dim];
        acc1 += X[o1 + dim];
        acc2 += X[o2 + dim];
        acc3 += X[o3 + dim];
    }
    for (; e < end; e++) acc0 += X[off2[e] + dim];
    float r = (acc0 + acc1) + (acc2 + acc3);
    hout[(size_t)v * DD + dim] = r > 0.f ? r : 0.f;
}

// ---------------------------------------------------------------------------
// GAT head, algebraically collapsed:
//   vl = Wg@al, vr = Wg@ar, vd = Wg@Wd   (tiny)
//   el/er/zd = h @ {vl, vr, vd}          (per node)
//   per node: softmax over in-edges of leaky(el[src]+er[v]); s_v = sum a_e*zd[src]
//   out[gid[v]] += s_v  (pool + dense head fused)
// ---------------------------------------------------------------------------
__global__ void __launch_bounds__(64) k_vecs(const float* __restrict__ Wg,
                                             const float* __restrict__ al,
                                             const float* __restrict__ ar,
                                             const float* __restrict__ Wd,
                                             float* __restrict__ vl,
                                             float* __restrict__ vr,
                                             float* __restrict__ vd) {
    int k = threadIdx.x;
    float sl = 0.f, sr = 0.f, sd = 0.f;
    #pragma unroll
    for (int o = 0; o < DD; o++) {
        float w = Wg[k * DD + o];
        sl += w * al[o];
        sr += w * ar[o];
        sd += w * Wd[o];
    }
    vl[k] = sl; vr[k] = sr; vd[k] = sd;
}

__global__ void __launch_bounds__(256) k_elerzd(const float* __restrict__ h,
                                                const float* __restrict__ vl,
                                                const float* __restrict__ vr,
                                                const float* __restrict__ vd,
                                                float* __restrict__ el,
                                                float* __restrict__ er,
                                                float* __restrict__ zd, int N) {
    int n = blockIdx.x * 256 + threadIdx.x;
    if (n >= N) return;
    const float* hp = h + (size_t)n * DD;
    float sl = 0.f, sr = 0.f, sd = 0.f;
    #pragma unroll
    for (int k = 0; k < DD; k++) {
        float hk = hp[k];
        sl += hk * vl[k];
        sr += hk * vr[k];
        sd += hk * vd[k];
    }
    el[n] = sl; er[n] = sr; zd[n] = sd;
}

__global__ void k_outinit(const float* __restrict__ bd, float* __restrict__ out, int B) {
    int b = blockIdx.x * blockDim.x + threadIdx.x;
    if (b < B) out[b] = bd[0];
}

__global__ void __launch_bounds__(64) k_gat(const float* __restrict__ el,
                                            const float* __restrict__ er,
                                            const float* __restrict__ zd,
                                            const int* __restrict__ rowptr,
                                            const int* __restrict__ src2,
                                            const int* __restrict__ gids,
                                            float* __restrict__ out, int N) {
    __shared__ float red[64];
    __shared__ float red2[64];
    int v = blockIdx.x;
    if (v >= N) return;
    int t = threadIdx.x;
    float erv = er[v];
    int beg = rowptr[v], end = rowptr[v + 1];

    // pass 1: segment max of leaky(el[src]+er[v])
    float m = -3.0e38f;
    for (int e = beg + t; e < end; e += 64) {
        float x = el[src2[e]] + erv;
        x = x > 0.f ? x : 0.2f * x;
        m = fmaxf(m, x);
    }
    red[t] = m;
    __syncthreads();
    #pragma unroll
    for (int off = 32; off > 0; off >>= 1) {
        if (t < off) red[t] = fmaxf(red[t], red[t + off]);
        __syncthreads();
    }
    m = red[0];
    __syncthreads();

    // pass 2: denominator + weighted sum of zd[src]
    float den = 0.f, num = 0.f;
    for (int e = beg + t; e < end; e += 64) {
        int s = src2[e];
        float x = el[s] + erv;
        x = x > 0.f ? x : 0.2f * x;
        float w = expf(x - m);
        den += w;
        num += w * zd[s];
    }
    red[t] = den; red2[t] = num;
    __syncthreads();
    #pragma unroll
    for (int off = 32; off > 0; off >>= 1) {
        if (t < off) { red[t] += red[t + off]; red2[t] += red2[t + off]; }
        __syncthreads();
    }
    if (t == 0) {
        float s = red2[0] / fmaxf(red[0], 1e-9f);
        atomicAdd(&out[gids[v]], s);
    }
}

// ---------------------------------------------------------------------------
// Launch: build CSR once, run 4 fused layers, GAT+pool+dense, all in-stream.
// ---------------------------------------------------------------------------
extern "C" void kernel_launch(void* const* d_in, const int* in_sizes, int n_in,
                              void* d_out, int out_size) {
    const float* h_in   = (const float*)d_in[0];
    const float* Wrel   = (const float*)d_in[1];
    const float* Wloop  = (const float*)d_in[2];
    const float* brel   = (const float*)d_in[3];
    const float* Wg     = (const float*)d_in[4];
    const float* al     = (const float*)d_in[5];
    const float* ar     = (const float*)d_in[6];
    const float* Wd     = (const float*)d_in[7];
    const float* bd     = (const float*)d_in[8];
    const int*   src    = (const int*)d_in[9];
    const int*   dst    = (const int*)d_in[10];
    const int*   etypes = (const int*)d_in[11];
    const int*   gids   = (const int*)d_in[12];
    float*       out    = (float*)d_out;

    const int N = in_sizes[0] / DD;
    const int E = in_sizes[9];
    const int L = in_sizes[2] / (DD * DD);
    const int B = out_size;

    // Resolve scratch symbol addresses (not a stream op; capture-safe).
    float *X, *h0, *h1, *elp, *erp, *zdp, *vl, *vr, *vd;
    int *rowptr, *cnt, *fill, *off2, *src2;
    cudaGetSymbolAddress((void**)&X,      g_X);
    cudaGetSymbolAddress((void**)&h0,     g_h0);
    cudaGetSymbolAddress((void**)&h1,     g_h1);
    cudaGetSymbolAddress((void**)&rowptr, g_rowptr);
    cudaGetSymbolAddress((void**)&cnt,    g_cnt);
    cudaGetSymbolAddress((void**)&fill,   g_fill);
    cudaGetSymbolAddress((void**)&off2,   g_off2);
    cudaGetSymbolAddress((void**)&src2,   g_src2);
    cudaGetSymbolAddress((void**)&elp,    g_el);
    cudaGetSymbolAddress((void**)&erp,    g_er);
    cudaGetSymbolAddress((void**)&zdp,    g_zd);
    cudaGetSymbolAddress((void**)&vl,     g_vl);
    cudaGetSymbolAddress((void**)&vr,     g_vr);
    cudaGetSymbolAddress((void**)&vd,     g_vd);

    const int EB = (E + 255) / 256;
    const int NB = (N + 255) / 256;

    // --- CSR by dst ---
    k_zero_int<<<NB, 256>>>(cnt, N);
    k_zero_int<<<NB, 256>>>(fill, N);
    k_hist<<<EB, 256>>>(dst, cnt, E);
    k_scan<<<1, 1024>>>(cnt, rowptr, N);
    k_scatter<<<EB, 256>>>(src, dst, etypes, rowptr, fill, off2, src2, E);

    // --- stacked RGCN layers ---
    const float* hcur = h_in;
    float* hnext = h0;
    const int GB = (N + 127) / 128;
    for (int l = 0; l < L; l++) {
        k_gemm<<<GB, 128>>>(hcur, Wrel + (size_t)l * RR * DD * DD,
                            Wloop + (size_t)l * DD * DD, X, N);
        k_agg<<<N, 64>>>(X, brel + (size_t)l * DD, rowptr, off2, hnext, N);
        hcur = hnext;
        hnext = (hnext == h0) ? h1 : h0;
    }

    // --- GAT head + SumPooling + dense, collapsed to scalars per node ---
    k_vecs<<<1, 64>>>(Wg, al, ar, Wd, vl, vr, vd);
    k_elerzd<<<NB, 256>>>(hcur, vl, vr, vd, elp, erp, zdp, N);
    k_outinit<<<1, 256>>>(bd, out, B);
    k_gat<<<N, 64>>>(elp, erp, zdp, rowptr, src2, gids, out, N);
}

// round 11
// speedup vs baseline: 1.0056x; 1.0009x over previous
#include <cuda_runtime.h>
#include <cuda_bf16.h>
#include <math.h>

// ---------------------------------------------------------------------------
// Problem constants (from reference): N=50000, E=1600000, D=64, R=4, L=4, B=256
// ---------------------------------------------------------------------------
#define DD 64
#define RR 4
#define NCOLS 320          // R*D (relation-transformed) + D (self-loop)
#define NMAX 50048
#define EMAX 1600512

// Scratch (static __device__ allocation is the sanctioned workaround)
__device__ float g_X[(size_t)NMAX * NCOLS];   // per-layer transformed features [N,320]
__device__ float g_h0[(size_t)NMAX * DD];
__device__ float g_h1[(size_t)NMAX * DD];
__device__ int   g_rowptr[NMAX + 1];
__device__ int   g_cnt[NMAX];
__device__ int   g_fill[NMAX];
__device__ int   g_off2[EMAX];                // src*320 + etype*64, CSR-ordered by dst
__device__ int   g_src2[EMAX];                // src, CSR-ordered by dst
__device__ float g_el[NMAX];
__device__ float g_er[NMAX];
__device__ float g_zd[NMAX];
__device__ float g_vl[DD];
__device__ float g_vr[DD];
__device__ float g_vd[DD];

// ---------------------------------------------------------------------------
// Preprocessing: CSR by destination
// ---------------------------------------------------------------------------
__global__ void k_zero_int(int* p, int n) {
    int i = blockIdx.x * blockDim.x + threadIdx.x;
    if (i < n) p[i] = 0;
}

__global__ void k_hist(const int* __restrict__ dst, int* __restrict__ cnt, int E) {
    int e = blockIdx.x * blockDim.x + threadIdx.x;
    if (e < E) atomicAdd(&cnt[dst[e]], 1);
}

__global__ void __launch_bounds__(1024) k_scan(const int* __restrict__ cnt,
                                               int* __restrict__ rowptr, int n) {
    __shared__ int sdata[1024];
    __shared__ int carry;
    int t = threadIdx.x;
    if (t == 0) { carry = 0; rowptr[0] = 0; }
    __syncthreads();
    for (int base = 0; base < n; base += 1024) {
        int i = base + t;
        int val = (i < n) ? cnt[i] : 0;
        sdata[t] = val;
        __syncthreads();
        #pragma unroll
        for (int off = 1; off < 1024; off <<= 1) {
            int y = (t >= off) ? sdata[t - off] : 0;
            __syncthreads();
            sdata[t] += y;
            __syncthreads();
        }
        int inc = sdata[t];
        int c = carry;
        if (i < n) rowptr[i + 1] = c + inc;
        __syncthreads();
        if (t == 1023) carry = c + sdata[1023];
        __syncthreads();
    }
}

__global__ void k_scatter(const int* __restrict__ src, const int* __restrict__ dst,
                          const int* __restrict__ et, const int* __restrict__ rowptr,
                          int* __restrict__ fill, int* __restrict__ off2,
                          int* __restrict__ src2, int E) {
    int e = blockIdx.x * blockDim.x + threadIdx.x;
    if (e >= E) return;
    int d = dst[e];
    int p = rowptr[d] + atomicAdd(&fill[d], 1);
    int s = src[e];
    off2[p] = s * NCOLS + et[e] * DD;
    src2[p] = s;
}

// ---------------------------------------------------------------------------
// Fused per-layer GEMM: X[n, 0:256] = h[n] @ Wrel[l] (4 relation blocks),
//                       X[n, 256:320] = h[n] @ Wloop[l]
// Thread-per-node, h row in registers, W tile broadcast from shared,
// packed fma.rn.f32x2 (2 fp32 MACs / FMA-pipe op).
// ---------------------------------------------------------------------------
__global__ void __launch_bounds__(128) k_gemm(const float* __restrict__ h,
                                              const float* __restrict__ Wrel_l,
                                              const float* __restrict__ Wloop_l,
                                              float* __restrict__ X, int N) {
    __shared__ float Ws[DD * DD];          // one [64,64] weight block (16 KB)
    int t = threadIdx.x;
    int node = blockIdx.x * 128 + t;
    bool valid = node < N;

    float hreg[DD];
    if (valid) {
        const float4* hp = reinterpret_cast<const float4*>(h + (size_t)node * DD);
        #pragma unroll
        for (int i = 0; i < 16; i++) {
            float4 v = hp[i];
            hreg[4 * i + 0] = v.x; hreg[4 * i + 1] = v.y;
            hreg[4 * i + 2] = v.z; hreg[4 * i + 3] = v.w;
        }
    } else {
        #pragma unroll
        for (int i = 0; i < DD; i++) hreg[i] = 0.f;
    }

    for (int chunk = 0; chunk < 5; chunk++) {
        const float* Wsrc = (chunk < 4) ? (Wrel_l + chunk * (DD * DD)) : Wloop_l;
        __syncthreads();
        #pragma unroll
        for (int i = 0; i < 8; i++) {     // 4096 floats = 1024 float4 / 128 threads
            reinterpret_cast<float4*>(Ws)[t + i * 128] =
                reinterpret_cast<const float4*>(Wsrc)[t + i * 128];
        }
        __syncthreads();

        #pragma unroll 1
        for (int cg = 0; cg < 8; cg++) {  // 8 output columns per group
            unsigned long long a0 = 0, a1 = 0, a2 = 0, a3 = 0;
            const float* wbase = Ws + cg * 8;
            #pragma unroll
            for (int k = 0; k < DD; k++) {
                unsigned long long h2;
                asm("mov.b64 %0, {%1, %1};" : "=l"(h2) : "f"(hreg[k]));
                ulonglong2 w01 = *reinterpret_cast<const ulonglong2*>(wbase + k * DD);
                ulonglong2 w23 = *reinterpret_cast<const ulonglong2*>(wbase + k * DD + 4);
                asm("fma.rn.f32x2 %0, %1, %2, %0;" : "+l"(a0) : "l"(h2), "l"(w01.x));
                asm("fma.rn.f32x2 %0, %1, %2, %0;" : "+l"(a1) : "l"(h2), "l"(w01.y));
                asm("fma.rn.f32x2 %0, %1, %2, %0;" : "+l"(a2) : "l"(h2), "l"(w23.x));
                asm("fma.rn.f32x2 %0, %1, %2, %0;" : "+l"(a3) : "l"(h2), "l"(w23.y));
            }
            if (valid) {
                ulonglong2* op = reinterpret_cast<ulonglong2*>(
                    X + (size_t)node * NCOLS + chunk * DD + cg * 8);
                op[0] = make_ulonglong2(a0, a1);
                op[1] = make_ulonglong2(a2, a3);
            }
        }
    }
}

// ---------------------------------------------------------------------------
// RGCN aggregation: one block (64 threads = feature dims) per node.
// acc = selfloop + bias + sum over CSR in-edges of X[src*320 + et*64 + dim]; ReLU.
// 4-way unroll with independent accumulators to expose memory-level parallelism.
// ---------------------------------------------------------------------------
__global__ void __launch_bounds__(64) k_agg(const float* __restrict__ X,
                                            const float* __restrict__ brel_l,
                                            const int* __restrict__ rowptr,
                                            const int* __restrict__ off2,
                                            float* __restrict__ hout, int N) {
    int v = blockIdx.x;
    if (v >= N) return;
    int dim = threadIdx.x;
    float acc0 = X[(size_t)v * NCOLS + RR * DD + dim] + brel_l[dim];
    float acc1 = 0.f, acc2 = 0.f, acc3 = 0.f;
    int e = rowptr[v], end = rowptr[v + 1];
    for (; e + 4 <= end; e += 4) {
        int o0 = off2[e], o1 = off2[e + 1], o2 = off2[e + 2], o3 = off2[e + 3];
        acc0 += X[o0 + dim];
        acc1 += X[o1 + dim];
        acc2 += X[o2 + dim];
        acc3 += X[o3 + dim];
    }
    for (; e < end; e++) acc0 += X[off2[e] + dim];
    float r = (acc0 + acc1) + (acc2 + acc3);
    hout[(size_t)v * DD + dim] = r > 0.f ? r : 0.f;
}

// ---------------------------------------------------------------------------
// GAT head, algebraically collapsed:
//   vl = Wg@al, vr = Wg@ar, vd = Wg@Wd   (tiny)
//   el/er/zd = h @ {vl, vr, vd}          (per node)
//   per node: softmax over in-edges of leaky(el[src]+er[v]); s_v = sum a_e*zd[src]
//   out[gid[v]] += s_v  (pool + dense head fused)
// ---------------------------------------------------------------------------
__global__ void __launch_bounds__(64) k_vecs(const float* __restrict__ Wg,
                                             const float* __restrict__ al,
                                             const float* __restrict__ ar,
                                             const float* __restrict__ Wd,
                                             float* __restrict__ vl,
                                             float* __restrict__ vr,
                                             float* __restrict__ vd) {
    int k = threadIdx.x;
    float sl = 0.f, sr = 0.f, sd = 0.f;
    #pragma unroll
    for (int o = 0; o < DD; o++) {
        float w = Wg[k * DD + o];
        sl += w * al[o];
        sr += w * ar[o];
        sd += w * Wd[o];
    }
    vl[k] = sl; vr[k] = sr; vd[k] = sd;
}

__global__ void __launch_bounds__(256) k_elerzd(const float* __restrict__ h,
                                                const float* __restrict__ vl,
                                                const float* __restrict__ vr,
                                                const float* __restrict__ vd,
                                                float* __restrict__ el,
                                                float* __restrict__ er,
                                                float* __restrict__ zd, int N) {
    int n = blockIdx.x * 256 + threadIdx.x;
    if (n >= N) return;
    const float* hp = h + (size_t)n * DD;
    float sl = 0.f, sr = 0.f, sd = 0.f;
    #pragma unroll
    for (int k = 0; k < DD; k++) {
        float hk = hp[k];
        sl += hk * vl[k];
        sr += hk * vr[k];
        sd += hk * vd[k];
    }
    el[n] = sl; er[n] = sr; zd[n] = sd;
}

__global__ void k_outinit(const float* __restrict__ bd, float* __restrict__ out, int B) {
    int b = blockIdx.x * blockDim.x + threadIdx.x;
    if (b < B) out[b] = bd[0];
}

__global__ void __launch_bounds__(64) k_gat(const float* __restrict__ el,
                                            const float* __restrict__ er,
                                            const float* __restrict__ zd,
                                            const int* __restrict__ rowptr,
                                            const int* __restrict__ src2,
                                            const int* __restrict__ gids,
                                            float* __restrict__ out, int N) {
    __shared__ float red[64];
    __shared__ float red2[64];
    int v = blockIdx.x;
    if (v >= N) return;
    int t = threadIdx.x;
    float erv = er[v];
    int beg = rowptr[v], end = rowptr[v + 1];

    // pass 1: segment max of leaky(el[src]+er[v])
    float m = -3.0e38f;
    for (int e = beg + t; e < end; e += 64) {
        float x = el[src2[e]] + erv;
        x = x > 0.f ? x : 0.2f * x;
        m = fmaxf(m, x);
    }
    red[t] = m;
    __syncthreads();
    #pragma unroll
    for (int off = 32; off > 0; off >>= 1) {
        if (t < off) red[t] = fmaxf(red[t], red[t + off]);
        __syncthreads();
    }
    m = red[0];
    __syncthreads();

    // pass 2: denominator + weighted sum of zd[src]
    float den = 0.f, num = 0.f;
    for (int e = beg + t; e < end; e += 64) {
        int s = src2[e];
        float x = el[s] + erv;
        x = x > 0.f ? x : 0.2f * x;
        float w = expf(x - m);
        den += w;
        num += w * zd[s];
    }
    red[t] = den; red2[t] = num;
    __syncthreads();
    #pragma unroll
    for (int off = 32; off > 0; off >>= 1) {
        if (t < off) { red[t] += red[t + off]; red2[t] += red2[t + off]; }
        __syncthreads();
    }
    if (t == 0) {
        float s = red2[0] / fmaxf(red[0], 1e-9f);
        atomicAdd(&out[gids[v]], s);
    }
}

// ---------------------------------------------------------------------------
// Launch: build CSR once, run 4 fused layers, GAT+pool+dense, all in-stream.
// ---------------------------------------------------------------------------
extern "C" void kernel_launch(void* const* d_in, const int* in_sizes, int n_in,
                              void* d_out, int out_size) {
    const float* h_in   = (const float*)d_in[0];
    const float* Wrel   = (const float*)d_in[1];
    const float* Wloop  = (const float*)d_in[2];
    const float* brel   = (const float*)d_in[3];
    const float* Wg     = (const float*)d_in[4];
    const float* al     = (const float*)d_in[5];
    const float* ar     = (const float*)d_in[6];
    const float* Wd     = (const float*)d_in[7];
    const float* bd     = (const float*)d_in[8];
    const int*   src    = (const int*)d_in[9];
    const int*   dst    = (const int*)d_in[10];
    const int*   etypes = (const int*)d_in[11];
    const int*   gids   = (const int*)d_in[12];
    float*       out    = (float*)d_out;

    const int N = in_sizes[0] / DD;
    const int E = in_sizes[9];
    const int L = in_sizes[2] / (DD * DD);
    const int B = out_size;

    // Resolve scratch symbol addresses (not a stream op; capture-safe).
    float *X, *h0, *h1, *elp, *erp, *zdp, *vl, *vr, *vd;
    int *rowptr, *cnt, *fill, *off2, *src2;
    cudaGetSymbolAddress((void**)&X,      g_X);
    cudaGetSymbolAddress((void**)&h0,     g_h0);
    cudaGetSymbolAddress((void**)&h1,     g_h1);
    cudaGetSymbolAddress((void**)&rowptr, g_rowptr);
    cudaGetSymbolAddress((void**)&cnt,    g_cnt);
    cudaGetSymbolAddress((void**)&fill,   g_fill);
    cudaGetSymbolAddress((void**)&off2,   g_off2);
    cudaGetSymbolAddress((void**)&src2,   g_src2);
    cudaGetSymbolAddress((void**)&elp,    g_el);
    cudaGetSymbolAddress((void**)&erp,    g_er);
    cudaGetSymbolAddress((void**)&zdp,    g_zd);
    cudaGetSymbolAddress((void**)&vl,     g_vl);
    cudaGetSymbolAddress((void**)&vr,     g_vr);
    cudaGetSymbolAddress((void**)&vd,     g_vd);

    const int EB = (E + 255) / 256;
    const int NB = (N + 255) / 256;

    // --- CSR by dst ---
    k_zero_int<<<NB, 256>>>(cnt, N);
    k_zero_int<<<NB, 256>>>(fill, N);
    k_hist<<<EB, 256>>>(dst, cnt, E);
    k_scan<<<1, 1024>>>(cnt, rowptr, N);
    k_scatter<<<EB, 256>>>(src, dst, etypes, rowptr, fill, off2, src2, E);

    // --- stacked RGCN layers ---
    const float* hcur = h_in;
    float* hnext = h0;
    const int GB = (N + 127) / 128;
    for (int l = 0; l < L; l++) {
        k_gemm<<<GB, 128>>>(hcur, Wrel + (size_t)l * RR * DD * DD,
                            Wloop + (size_t)l * DD * DD, X, N);
        k_agg<<<N, 64>>>(X, brel + (size_t)l * DD, rowptr, off2, hnext, N);
        hcur = hnext;
        hnext = (hnext == h0) ? h1 : h0;
    }

    // --- GAT head + SumPooling + dense, collapsed to scalars per node ---
    k_vecs<<<1, 64>>>(Wg, al, ar, Wd, vl, vr, vd);
    k_elerzd<<<NB, 256>>>(hcur, vl, vr, vd, elp, erp, zdp, N);
    k_outinit<<<1, 256>>>(bd, out, B);
    k_gat<<<N, 64>>>(elp, erp, zdp, rowptr, src2, gids, out, N);
}